// round 6
// baseline (speedup 1.0000x reference)
#include <cuda_runtime.h>
#include <math.h>

// ---------------------------------------------------------------------------
// MinkNeXtBlock: x -> 1x1conv -> LN+GELU -> sparse_conv3(W1) -> LN+GELU
//                  -> sparse_conv3(W2) -> LN -> +x -> GELU
// N=100000 rows, Cin=32, Cmid=128, K=27 neighbor offsets.
// ---------------------------------------------------------------------------

#define NMAX 100000
#define KK   27

// Scratch (device globals: no allocation allowed in kernel_launch)
__device__ float g_h0[NMAX * 32];    // after conv0+LN+GELU      (12.8 MB)
__device__ float g_h1[NMAX * 128];   // after conv1+LN+GELU      (51.2 MB)
__device__ int   g_mask_w4;          // 1 if mask stored as int32, 0 if 1-byte

// ---------------------------------------------------------------------------

__device__ __forceinline__ float gelu_f(float v) {
    // exact (erf) gelu, matching jax.nn.gelu(approximate=False)
    return 0.5f * v * (1.0f + erff(v * 0.70710678118654752f));
}

__device__ __forceinline__ unsigned long long splat2(float x) {
    unsigned long long r; unsigned int u = __float_as_uint(x);
    asm("mov.b64 %0, {%1, %1};" : "=l"(r) : "r"(u));
    return r;
}
__device__ __forceinline__ void fma2(unsigned long long& d,
                                     unsigned long long a, unsigned long long b) {
    asm("fma.rn.f32x2 %0, %1, %2, %0;" : "+l"(d) : "l"(a), "l"(b));
}
__device__ __forceinline__ float2 unpk(unsigned long long v) {
    unsigned int lo, hi;
    asm("mov.b64 {%0, %1}, %2;" : "=r"(lo), "=r"(hi) : "l"(v));
    return make_float2(__uint_as_float(lo), __uint_as_float(hi));
}

// Read mask element robustly (byte layout or int32 layout, detected at runtime)
__device__ __forceinline__ int mask_at(const void* m, int off, int w4) {
    if (w4) return ((const int*)m)[off];
    return (int)((const unsigned char*)m)[off];
}

// ---------------------------------------------------------------------------
// Kernel 0: h0 = gelu(LN(x @ Wc)); one warp per row. Also detects mask layout.
// ---------------------------------------------------------------------------
__global__ void k_conv0(const float* __restrict__ x, const float* __restrict__ Wc,
                        const float* __restrict__ g0, const float* __restrict__ b0,
                        const unsigned char* __restrict__ maskraw, int n) {
    __shared__ float sW[32 * 32];
    int tid = threadIdx.x;
    if (blockIdx.x == 0 && tid == 0) {
        // If mask is int32 (values 0/1, little-endian), all bytes at offsets
        // not divisible by 4 are zero. If it is 1-byte bool, ~half of the
        // first few hundred bytes are 1 (prob of false negative ~2^-150).
        int w4 = 1;
        for (int t = 1; t < 400; ++t) {
            if ((t & 3) != 0 && maskraw[t] != 0) { w4 = 0; break; }
        }
        g_mask_w4 = w4;
    }
    for (int i = tid; i < 1024; i += 256) sW[i] = Wc[i];
    __syncthreads();

    int lane = tid & 31, w = tid >> 5;
    int row = blockIdx.x * 8 + w;
    if (row >= n) return;

    float xv = x[row * 32 + lane];
    float acc = 0.0f;
#pragma unroll
    for (int c = 0; c < 32; ++c) {
        float xs = __shfl_sync(0xffffffffu, xv, c);
        acc = fmaf(xs, sW[c * 32 + lane], acc);
    }
    // LayerNorm over 32 channels (one per lane)
    float s = acc;
#pragma unroll
    for (int o = 16; o > 0; o >>= 1) s += __shfl_xor_sync(0xffffffffu, s, o);
    float mu = s * (1.0f / 32.0f);
    float d = acc - mu;
    float q = d * d;
#pragma unroll
    for (int o = 16; o > 0; o >>= 1) q += __shfl_xor_sync(0xffffffffu, q, o);
    float var = q * (1.0f / 32.0f);
    float y = d * rsqrtf(var + 1e-6f) * g0[lane] + b0[lane];
    g_h0[row * 32 + lane] = gelu_f(y);
}

// ---------------------------------------------------------------------------
// Kernel 1: h1 = gelu(LN(sparse_conv3(h0, W1)))    Cin=32 -> Cout=128
// 128-row tiles, 256 threads, 8x8 outputs/thread, fma.rn.f32x2 inner loop.
// ---------------------------------------------------------------------------
__global__ void __launch_bounds__(256, 2)
k_conv1(const float* __restrict__ W1, const int* __restrict__ nidx,
        const void* __restrict__ nmask,
        const float* __restrict__ g1, const float* __restrict__ b1, int n) {
    __shared__ union {
        struct { float A[32][128]; float W[32][128]; } s;  // 32 KB
        float red[2][128][17];                              // 17.4 KB (epilogue)
    } u;
    __shared__ int sidx[KK * 128];   // masked neighbor index, -1 = skip

    int tid = threadIdx.x;
    int row0 = blockIdx.x * 128;
    int w4 = g_mask_w4;

    for (int t = tid; t < KK * 128; t += 256) {
        int m = t / KK, k = t % KK;
        int nr = row0 + m;
        int id = -1;
        if (nr < n) {
            int off = nr * KK + k;
            if (mask_at(nmask, off, w4)) id = nidx[off];
        }
        sidx[k * 128 + m] = id;
    }

    int ty = tid >> 4, tx = tid & 15;         // rows ty*8.., cols tx*8..
    float gg[8], bb[8];
#pragma unroll
    for (int j = 0; j < 8; ++j) { gg[j] = g1[tx * 8 + j]; bb[j] = b1[tx * 8 + j]; }

    unsigned long long acc[4][8];             // [row-pair][col], f32x2 packed
#pragma unroll
    for (int p = 0; p < 4; ++p)
#pragma unroll
        for (int j = 0; j < 8; ++j) acc[p][j] = 0ull;

    int gm = tid & 127, gcb = tid >> 7;       // gather: my row & base col-group

    for (int k = 0; k < KK; ++k) {
        __syncthreads();
        // stage W1[k]: 32x128 floats
        {
            const float4* src = (const float4*)(W1 + k * (32 * 128));
            float4* dst = (float4*)&u.s.W[0][0];
#pragma unroll
            for (int i = 0; i < 4; ++i) dst[tid + i * 256] = src[tid + i * 256];
        }
        // gather A (transposed: A[c][m]) with mask/zero fill
        {
            int id = sidx[k * 128 + gm];
            const float4* srow = (const float4*)(g_h0 + (id >= 0 ? id : 0) * 32);
#pragma unroll
            for (int i = 0; i < 4; ++i) {
                int cg = gcb + 2 * i;         // 0..7
                float4 v = make_float4(0.f, 0.f, 0.f, 0.f);
                if (id >= 0) v = srow[cg];
                u.s.A[cg * 4 + 0][gm] = v.x;
                u.s.A[cg * 4 + 1][gm] = v.y;
                u.s.A[cg * 4 + 2][gm] = v.z;
                u.s.A[cg * 4 + 3][gm] = v.w;
            }
        }
        __syncthreads();
#pragma unroll
        for (int c = 0; c < 32; ++c) {
            const ulonglong2* ap = (const ulonglong2*)&u.s.A[c][ty * 8];
            ulonglong2 A0 = ap[0], A1 = ap[1];
            unsigned long long apair[4] = { A0.x, A0.y, A1.x, A1.y };
            const float4* wp = (const float4*)&u.s.W[c][tx * 8];
            float4 w0 = wp[0], w1 = wp[1];
            float ws[8] = { w0.x, w0.y, w0.z, w0.w, w1.x, w1.y, w1.z, w1.w };
#pragma unroll
            for (int j = 0; j < 8; ++j) {
                unsigned long long wsp = splat2(ws[j]);
#pragma unroll
                for (int p = 0; p < 4; ++p) fma2(acc[p][j], apair[p], wsp);
            }
        }
    }

    // unpack: row i = ty*8 + 2p + (lo/hi), col = tx*8 + j
    float vv[8][8];
#pragma unroll
    for (int p = 0; p < 4; ++p)
#pragma unroll
        for (int j = 0; j < 8; ++j) {
            float2 t = unpk(acc[p][j]);
            vv[2 * p][j] = t.x; vv[2 * p + 1][j] = t.y;
        }

    __syncthreads();   // everyone done reading A/W before red overwrites them
#pragma unroll
    for (int i = 0; i < 8; ++i) {
        float ps = 0.f, pq = 0.f;
#pragma unroll
        for (int j = 0; j < 8; ++j) { float v = vv[i][j]; ps += v; pq = fmaf(v, v, pq); }
        u.red[0][ty * 8 + i][tx] = ps;
        u.red[1][ty * 8 + i][tx] = pq;
    }
    __syncthreads();
#pragma unroll
    for (int i = 0; i < 8; ++i) {
        int r = ty * 8 + i;
        int nr = row0 + r;
        if (nr >= n) continue;
        float s = 0.f, q = 0.f;
#pragma unroll
        for (int t = 0; t < 16; ++t) { s += u.red[0][r][t]; q += u.red[1][r][t]; }
        float mu = s * (1.0f / 128.0f);
        float var = q * (1.0f / 128.0f) - mu * mu;
        float rs = rsqrtf(var + 1e-6f);
        float ov[8];
#pragma unroll
        for (int j = 0; j < 8; ++j) {
            float y = (vv[i][j] - mu) * rs * gg[j] + bb[j];
            ov[j] = gelu_f(y);
        }
        float4* dst = (float4*)(g_h1 + (size_t)nr * 128 + tx * 8);
        dst[0] = make_float4(ov[0], ov[1], ov[2], ov[3]);
        dst[1] = make_float4(ov[4], ov[5], ov[6], ov[7]);
    }
}

// ---------------------------------------------------------------------------
// Kernel 2: out = gelu(LN(sparse_conv3(h1, W2)) + x)    Cin=128 -> Cout=32
// 128-row tiles, 256 threads, 8x2 outputs/thread. Dynamic smem (~94 KB).
// ---------------------------------------------------------------------------
struct SmemC2 {
    union {
        float A[128][128];          // 64 KB   [c][m]
        float red[2][128][17];      // 17.4 KB (epilogue)
    };
    float W[128][32];               // 16 KB   [c][d]
    int   sidx[KK * 128];           // 13.5 KB
};

__global__ void __launch_bounds__(256, 2)
k_conv2(const float* __restrict__ x, const float* __restrict__ W2,
        const int* __restrict__ nidx, const void* __restrict__ nmask,
        const float* __restrict__ g2, const float* __restrict__ b2,
        float* __restrict__ out, int n) {
    extern __shared__ char dynsmem[];
    SmemC2& sm = *(SmemC2*)dynsmem;

    int tid = threadIdx.x;
    int row0 = blockIdx.x * 128;
    int w4 = g_mask_w4;

    for (int t = tid; t < KK * 128; t += 256) {
        int m = t / KK, k = t % KK;
        int nr = row0 + m;
        int id = -1;
        if (nr < n) {
            int off = nr * KK + k;
            if (mask_at(nmask, off, w4)) id = nidx[off];
        }
        sm.sidx[k * 128 + m] = id;
    }

    int ty = tid >> 4, tx = tid & 15;         // rows ty*8.., cols tx*2..
    float gg0 = g2[tx * 2], gg1 = g2[tx * 2 + 1];
    float bb0 = b2[tx * 2], bb1 = b2[tx * 2 + 1];

    unsigned long long acc[4][2];             // [row-pair][col]
#pragma unroll
    for (int p = 0; p < 4; ++p) { acc[p][0] = 0ull; acc[p][1] = 0ull; }

    int gm = tid & 127, gcb = tid >> 7;

    for (int k = 0; k < KK; ++k) {
        __syncthreads();
        // stage W2[k]: 128x32 floats
        {
            const float4* src = (const float4*)(W2 + k * (128 * 32));
            float4* dst = (float4*)&sm.W[0][0];
#pragma unroll
            for (int i = 0; i < 4; ++i) dst[tid + i * 256] = src[tid + i * 256];
        }
        // gather A[c][m]: each thread copies half of one 512B row
        {
            int id = sm.sidx[k * 128 + gm];
            const float4* srow = (const float4*)(g_h1 + (size_t)(id >= 0 ? id : 0) * 128);
#pragma unroll
            for (int i = 0; i < 16; ++i) {
                int cg = gcb + 2 * i;         // 0..31
                float4 v = make_float4(0.f, 0.f, 0.f, 0.f);
                if (id >= 0) v = srow[cg];
                sm.A[cg * 4 + 0][gm] = v.x;
                sm.A[cg * 4 + 1][gm] = v.y;
                sm.A[cg * 4 + 2][gm] = v.z;
                sm.A[cg * 4 + 3][gm] = v.w;
            }
        }
        __syncthreads();
#pragma unroll 8
        for (int c = 0; c < 128; ++c) {
            const ulonglong2* ap = (const ulonglong2*)&sm.A[c][ty * 8];
            ulonglong2 A0 = ap[0], A1 = ap[1];
            unsigned long long apair[4] = { A0.x, A0.y, A1.x, A1.y };
            float2 w = *(const float2*)&sm.W[c][tx * 2];
            unsigned long long ws0 = splat2(w.x), ws1 = splat2(w.y);
#pragma unroll
            for (int p = 0; p < 4; ++p) {
                fma2(acc[p][0], apair[p], ws0);
                fma2(acc[p][1], apair[p], ws1);
            }
        }
    }

    float vv[8][2];
#pragma unroll
    for (int p = 0; p < 4; ++p)
#pragma unroll
        for (int j = 0; j < 2; ++j) {
            float2 t = unpk(acc[p][j]);
            vv[2 * p][j] = t.x; vv[2 * p + 1][j] = t.y;
        }

    __syncthreads();
#pragma unroll
    for (int i = 0; i < 8; ++i) {
        float v0 = vv[i][0], v1 = vv[i][1];
        sm.red[0][ty * 8 + i][tx] = v0 + v1;
        sm.red[1][ty * 8 + i][tx] = v0 * v0 + v1 * v1;
    }
    __syncthreads();
#pragma unroll
    for (int i = 0; i < 8; ++i) {
        int r = ty * 8 + i;
        int nr = row0 + r;
        if (nr >= n) continue;
        float s = 0.f, q = 0.f;
#pragma unroll
        for (int t = 0; t < 16; ++t) { s += sm.red[0][r][t]; q += sm.red[1][r][t]; }
        float mu = s * (1.0f / 32.0f);
        float var = q * (1.0f / 32.0f) - mu * mu;
        float rs = rsqrtf(var + 1e-6f);
        float2 xres = *(const float2*)(x + nr * 32 + tx * 2);
        float y0 = (vv[i][0] - mu) * rs * gg0 + bb0 + xres.x;
        float y1 = (vv[i][1] - mu) * rs * gg1 + bb1 + xres.y;
        *(float2*)(out + nr * 32 + tx * 2) = make_float2(gelu_f(y0), gelu_f(y1));
    }
}

// ---------------------------------------------------------------------------

extern "C" void kernel_launch(void* const* d_in, const int* in_sizes, int n_in,
                              void* d_out, int out_size) {
    const float* x   = (const float*)d_in[0];
    const int*   nid = (const int*)d_in[1];
    const void*  msk = (const void*)d_in[2];
    const float* Wc  = (const float*)d_in[3];
    const float* g0  = (const float*)d_in[4];
    const float* b0  = (const float*)d_in[5];
    const float* W1  = (const float*)d_in[6];
    const float* g1  = (const float*)d_in[7];
    const float* b1  = (const float*)d_in[8];
    const float* W2  = (const float*)d_in[9];
    const float* g2  = (const float*)d_in[10];
    const float* b2  = (const float*)d_in[11];
    float* out = (float*)d_out;
    int n = in_sizes[0] / 32;

    cudaFuncSetAttribute(k_conv2, cudaFuncAttributeMaxDynamicSharedMemorySize,
                         (int)sizeof(SmemC2));

    k_conv0<<<(n + 7) / 8, 256>>>(x, Wc, g0, b0, (const unsigned char*)msk, n);
    int nb = (n + 127) / 128;
    k_conv1<<<nb, 256>>>(W1, nid, msk, g1, b1, n);
    k_conv2<<<nb, 256, sizeof(SmemC2)>>>(x, W2, nid, msk, g2, b2, out, n);
}